// round 2
// baseline (speedup 1.0000x reference)
#include <cuda_runtime.h>
#include <cuda_bf16.h>
#include <math.h>

#define SEQ 2048
#define BATCH 2
#define DMODEL 1024
#define NHEAD 16
#define HDIM 64
#define MROWS (SEQ * BATCH)   // 4096

// Scratch (no cudaMalloc allowed): Q, K, V, CTX activations, fp32.
__device__ float g_q[MROWS * DMODEL];
__device__ float g_k[MROWS * DMODEL];
__device__ float g_v[MROWS * DMODEL];
__device__ float g_ctx[MROWS * DMODEL];

// C[M,N] = A[M,K] @ W[N,K]^T + bias ; M=4096, N=K=1024.
// 64x64 block tile, BK=16, 256 threads, 4x4 micro-tile per thread.
__global__ __launch_bounds__(256) void gemm_bias_kernel(
    const float* __restrict__ A, const float* __restrict__ W,
    const float* __restrict__ bias, float* __restrict__ C)
{
    __shared__ float As[16][64];
    __shared__ float Bs[16][64];
    const int tid = threadIdx.x;
    const int tx = tid & 15;      // 0..15 -> N group
    const int ty = tid >> 4;      // 0..15 -> M group
    const int rowBase = blockIdx.y * 64;
    const int colBase = blockIdx.x * 64;
    const int lr = tid >> 2;      // 0..63 load row
    const int lc = tid & 3;       // 0..3  load float4-col

    const float* Ap = A + (size_t)(rowBase + lr) * DMODEL + lc * 4;
    const float* Wp = W + (size_t)(colBase + lr) * DMODEL + lc * 4;

    float acc[4][4];
    #pragma unroll
    for (int i = 0; i < 4; i++)
        #pragma unroll
        for (int j = 0; j < 4; j++) acc[i][j] = 0.0f;

    for (int k0 = 0; k0 < DMODEL; k0 += 16) {
        float4 av = *(const float4*)(Ap + k0);
        float4 wv = *(const float4*)(Wp + k0);
        As[lc * 4 + 0][lr] = av.x; As[lc * 4 + 1][lr] = av.y;
        As[lc * 4 + 2][lr] = av.z; As[lc * 4 + 3][lr] = av.w;
        Bs[lc * 4 + 0][lr] = wv.x; Bs[lc * 4 + 1][lr] = wv.y;
        Bs[lc * 4 + 2][lr] = wv.z; Bs[lc * 4 + 3][lr] = wv.w;
        __syncthreads();
        #pragma unroll
        for (int k = 0; k < 16; k++) {
            float4 a4 = *(const float4*)&As[k][ty * 4];
            float4 b4 = *(const float4*)&Bs[k][tx * 4];
            float ar[4] = {a4.x, a4.y, a4.z, a4.w};
            float br[4] = {b4.x, b4.y, b4.z, b4.w};
            #pragma unroll
            for (int i = 0; i < 4; i++)
                #pragma unroll
                for (int j = 0; j < 4; j++)
                    acc[i][j] += ar[i] * br[j];
        }
        __syncthreads();
    }

    float4 bb = *(const float4*)&bias[colBase + tx * 4];
    #pragma unroll
    for (int i = 0; i < 4; i++) {
        float4 o = make_float4(acc[i][0] + bb.x, acc[i][1] + bb.y,
                               acc[i][2] + bb.z, acc[i][3] + bb.w);
        *(float4*)&C[(size_t)(rowBase + ty * 4 + i) * DMODEL + colBase + tx * 4] = o;
    }
}

// Flash attention, causal, fp32. One query row per thread (64 rows/block).
// Key/value tiles of 32 in smem; online softmax updated per 8-key group.
__global__ __launch_bounds__(64) void attn_kernel()
{
    const int tid = threadIdx.x;                    // 0..63
    const int qTile = (gridDim.x - 1) - blockIdx.x; // heavy tiles first
    const int b = blockIdx.y & (BATCH - 1);
    const int h = blockIdx.y / BATCH;
    const int s = qTile * 64 + tid;

    __shared__ float Ks[32][64];
    __shared__ float Vs[32][64];

    float q[64], acc[64];
    const float* qp = g_q + (size_t)(s * BATCH + b) * DMODEL + h * HDIM;
    #pragma unroll
    for (int d4 = 0; d4 < 16; d4++) {
        float4 v = *(const float4*)(qp + d4 * 4);
        q[d4 * 4 + 0] = v.x * 0.125f;  // 1/sqrt(64)
        q[d4 * 4 + 1] = v.y * 0.125f;
        q[d4 * 4 + 2] = v.z * 0.125f;
        q[d4 * 4 + 3] = v.w * 0.125f;
        acc[d4 * 4 + 0] = 0.f; acc[d4 * 4 + 1] = 0.f;
        acc[d4 * 4 + 2] = 0.f; acc[d4 * 4 + 3] = 0.f;
    }
    float mrun = -1e30f, lrun = 0.0f;

    const int numKT = 2 * qTile + 2;   // key tiles of 32 covering 0..qTile*64+63
    for (int kt = 0; kt < numKT; kt++) {
        const int t0 = kt * 32;
        // cooperative load: 32x64 K and V tiles (each thread 8 float4 per tile)
        #pragma unroll
        for (int i = 0; i < 8; i++) {
            int idx = tid + i * 64;            // 0..511 float4 slots
            int r = idx >> 4;
            int c = (idx & 15) * 4;
            size_t goff = (size_t)((t0 + r) * BATCH + b) * DMODEL + h * HDIM + c;
            *(float4*)&Ks[r][c] = *(const float4*)(g_k + goff);
            *(float4*)&Vs[r][c] = *(const float4*)(g_v + goff);
        }
        __syncthreads();

        #pragma unroll 1
        for (int g = 0; g < 4; g++) {
            float sc[8];
            float tmax = -1e30f;
            #pragma unroll
            for (int jj = 0; jj < 8; jj++) {
                const int j = g * 8 + jj;
                const float4* kr = (const float4*)Ks[j];
                float s0 = 0.f, s1 = 0.f, s2 = 0.f, s3 = 0.f;
                #pragma unroll
                for (int d4 = 0; d4 < 16; d4++) {
                    float4 kk = kr[d4];
                    s0 += q[d4 * 4 + 0] * kk.x;
                    s1 += q[d4 * 4 + 1] * kk.y;
                    s2 += q[d4 * 4 + 2] * kk.z;
                    s3 += q[d4 * 4 + 3] * kk.w;
                }
                float sum = (s0 + s1) + (s2 + s3);
                sc[jj] = (t0 + j <= s) ? sum : -1e30f;   // causal mask
                tmax = fmaxf(tmax, sc[jj]);
            }
            float mnew = fmaxf(mrun, tmax);
            float corr = __expf(mrun - mnew);
            lrun *= corr;
            #pragma unroll
            for (int d = 0; d < 64; d++) acc[d] *= corr;
            #pragma unroll
            for (int jj = 0; jj < 8; jj++) {
                float p = __expf(sc[jj] - mnew);
                lrun += p;
                const float4* vr = (const float4*)Vs[g * 8 + jj];
                #pragma unroll
                for (int d4 = 0; d4 < 16; d4++) {
                    float4 vv = vr[d4];
                    acc[d4 * 4 + 0] += p * vv.x;
                    acc[d4 * 4 + 1] += p * vv.y;
                    acc[d4 * 4 + 2] += p * vv.z;
                    acc[d4 * 4 + 3] += p * vv.w;
                }
            }
            mrun = mnew;
        }
        __syncthreads();
    }

    const float inv = 1.0f / lrun;
    float* op = g_ctx + (size_t)(s * BATCH + b) * DMODEL + h * HDIM;
    #pragma unroll
    for (int d4 = 0; d4 < 16; d4++) {
        float4 o = make_float4(acc[d4 * 4 + 0] * inv, acc[d4 * 4 + 1] * inv,
                               acc[d4 * 4 + 2] * inv, acc[d4 * 4 + 3] * inv);
        *(float4*)(op + d4 * 4) = o;
    }
}

extern "C" void kernel_launch(void* const* d_in, const int* in_sizes, int n_in,
                              void* d_out, int out_size)
{
    const float* x  = (const float*)d_in[0];
    const float* qw = (const float*)d_in[1];
    const float* qb = (const float*)d_in[2];
    const float* kw = (const float*)d_in[3];
    const float* kb = (const float*)d_in[4];
    const float* vw = (const float*)d_in[5];
    const float* vb = (const float*)d_in[6];
    const float* ow = (const float*)d_in[7];
    const float* ob = (const float*)d_in[8];
    // d_in[9] = attn_mask: known causal mask, applied analytically in attn_kernel.
    float* out = (float*)d_out;

    void *pq, *pk, *pv, *pc;
    cudaGetSymbolAddress(&pq, g_q);
    cudaGetSymbolAddress(&pk, g_k);
    cudaGetSymbolAddress(&pv, g_v);
    cudaGetSymbolAddress(&pc, g_ctx);

    dim3 gg(DMODEL / 64, MROWS / 64);   // (16, 64)
    gemm_bias_kernel<<<gg, 256>>>(x, qw, qb, (float*)pq);
    gemm_bias_kernel<<<gg, 256>>>(x, kw, kb, (float*)pk);
    gemm_bias_kernel<<<gg, 256>>>(x, vw, vb, (float*)pv);
    attn_kernel<<<dim3(SEQ / 64, BATCH * NHEAD), 64>>>();
    gemm_bias_kernel<<<gg, 256>>>((const float*)pc, ow, ob, out);
}

// round 3
// speedup vs baseline: 3.1888x; 3.1888x over previous
#include <cuda_runtime.h>
#include <cuda_bf16.h>
#include <math.h>

#define SEQ 2048
#define BATCH 2
#define DMODEL 1024
#define NHEAD 16
#define HDIM 64
#define MROWS (SEQ * BATCH)   // 4096

// Scratch (no cudaMalloc allowed)
__device__ float g_q[MROWS * DMODEL];
__device__ float g_k[MROWS * DMODEL];
__device__ float g_v[MROWS * DMODEL];
__device__ float g_ctx[MROWS * DMODEL];

// ---------------- helpers ----------------
__device__ __forceinline__ unsigned f2tf(float f) {
    unsigned u;
    asm("cvt.rna.tf32.f32 %0, %1;" : "=r"(u) : "f"(f));
    return u;
}

__device__ __forceinline__ void mma_tf32(
    float& c0, float& c1, float& c2, float& c3,
    unsigned a0, unsigned a1, unsigned a2, unsigned a3,
    unsigned b0, unsigned b1)
{
    asm volatile(
        "mma.sync.aligned.m16n8k8.row.col.f32.tf32.tf32.f32 "
        "{%0,%1,%2,%3},{%4,%5,%6,%7},{%8,%9},{%0,%1,%2,%3};"
        : "+f"(c0), "+f"(c1), "+f"(c2), "+f"(c3)
        : "r"(a0), "r"(a1), "r"(a2), "r"(a3), "r"(b0), "r"(b1));
}

__device__ __forceinline__ void cpa16(void* dst, const void* src) {
    unsigned d = (unsigned)__cvta_generic_to_shared(dst);
    asm volatile("cp.async.cg.shared.global [%0], [%1], 16;" :: "r"(d), "l"(src));
}
#define CP_COMMIT() asm volatile("cp.async.commit_group;")
#define CP_WAIT1()  asm volatile("cp.async.wait_group 1;")
#define CP_WAIT0()  asm volatile("cp.async.wait_group 0;")

// ---------------- GEMM: C[M,N] = A[M,K] @ W[N,K]^T + bias ----------------
// M=4096, N=K=1024. Block tile 128x128, BK=16, 256 threads (8 warps, 4x2),
// warp tile 32x64 (2 m-tiles x 8 n-tiles of m16n8k8 tf32).
#define GBK 16
#define GST 20   // GBK + 4 pad -> conflict-free frag loads

__global__ __launch_bounds__(256) void gemm_tf32(
    const float* __restrict__ A, const float* __restrict__ W,
    const float* __restrict__ bias, float* __restrict__ C)
{
    __shared__ float As[2][128][GST];
    __shared__ float Bs[2][128][GST];
    const int tid = threadIdx.x;
    const int lane = tid & 31;
    const int wid = tid >> 5;
    const int wm = wid & 3;       // 0..3
    const int wn = wid >> 2;      // 0..1
    const int g = lane >> 2, t = lane & 3;
    const int rowBase = blockIdx.y * 128;
    const int colBase = blockIdx.x * 128;

    const int lr0 = tid >> 2;           // 0..63
    const int lc = (tid & 3) * 4;       // float4 col
    const float* Ag = A + (size_t)(rowBase + lr0) * DMODEL + lc;
    const float* Wg = W + (size_t)(colBase + lr0) * DMODEL + lc;

    float c[2][8][4];
    #pragma unroll
    for (int mt = 0; mt < 2; mt++)
        #pragma unroll
        for (int nt = 0; nt < 8; nt++)
            #pragma unroll
            for (int i = 0; i < 4; i++) c[mt][nt][i] = 0.0f;

    // prologue
    {
        cpa16(&As[0][lr0][lc],      Ag);
        cpa16(&As[0][lr0 + 64][lc], Ag + (size_t)64 * DMODEL);
        cpa16(&Bs[0][lr0][lc],      Wg);
        cpa16(&Bs[0][lr0 + 64][lc], Wg + (size_t)64 * DMODEL);
        CP_COMMIT();
    }

    const int NIT = DMODEL / GBK;   // 64
    for (int it = 0; it < NIT; it++) {
        if (it + 1 < NIT) {
            const int sn = (it + 1) & 1;
            const int k0 = (it + 1) * GBK;
            cpa16(&As[sn][lr0][lc],      Ag + k0);
            cpa16(&As[sn][lr0 + 64][lc], Ag + (size_t)64 * DMODEL + k0);
            cpa16(&Bs[sn][lr0][lc],      Wg + k0);
            cpa16(&Bs[sn][lr0 + 64][lc], Wg + (size_t)64 * DMODEL + k0);
            CP_COMMIT();
            CP_WAIT1();
        } else {
            CP_WAIT0();
        }
        __syncthreads();
        const int s = it & 1;
        #pragma unroll
        for (int ks = 0; ks < 2; ks++) {
            const int kk = ks * 8;
            unsigned a[2][4], bf[8][2];
            #pragma unroll
            for (int mt = 0; mt < 2; mt++) {
                const int r = wm * 32 + mt * 16;
                a[mt][0] = f2tf(As[s][r + g][kk + t]);
                a[mt][1] = f2tf(As[s][r + 8 + g][kk + t]);
                a[mt][2] = f2tf(As[s][r + g][kk + 4 + t]);
                a[mt][3] = f2tf(As[s][r + 8 + g][kk + 4 + t]);
            }
            #pragma unroll
            for (int nt = 0; nt < 8; nt++) {
                const int n = wn * 64 + nt * 8;
                bf[nt][0] = f2tf(Bs[s][n + g][kk + t]);
                bf[nt][1] = f2tf(Bs[s][n + g][kk + 4 + t]);
            }
            #pragma unroll
            for (int mt = 0; mt < 2; mt++)
                #pragma unroll
                for (int nt = 0; nt < 8; nt++)
                    mma_tf32(c[mt][nt][0], c[mt][nt][1], c[mt][nt][2], c[mt][nt][3],
                             a[mt][0], a[mt][1], a[mt][2], a[mt][3],
                             bf[nt][0], bf[nt][1]);
        }
        __syncthreads();
    }

    // epilogue: bias + store (float2 per pair)
    #pragma unroll
    for (int mt = 0; mt < 2; mt++) {
        const int r0 = rowBase + wm * 32 + mt * 16 + g;
        #pragma unroll
        for (int nt = 0; nt < 8; nt++) {
            const int col = colBase + wn * 64 + nt * 8 + 2 * t;
            float2 bb = *(const float2*)&bias[col];
            float2 o0 = make_float2(c[mt][nt][0] + bb.x, c[mt][nt][1] + bb.y);
            float2 o1 = make_float2(c[mt][nt][2] + bb.x, c[mt][nt][3] + bb.y);
            *(float2*)&C[(size_t)r0 * DMODEL + col] = o0;
            *(float2*)&C[(size_t)(r0 + 8) * DMODEL + col] = o1;
        }
    }
}

// ---------------- Flash attention (causal), tf32 mma ----------------
// One (b,h,qtile of 64 rows) per block. 128 threads, 4 warps; warp w owns
// q rows [16w,16w+16). QK^T and PV both via m16n8k8 tf32. P staged through
// warp-private smem rows. K/V tiles double-buffered with cp.async.
#define AST 68   // 64 + 4 pad

__global__ __launch_bounds__(128) void attn_tf32()
{
    extern __shared__ float sm[];
    float (*Ks)[64][AST] = (float (*)[64][AST])sm;
    float (*Vs)[64][AST] = (float (*)[64][AST])(sm + 2 * 64 * AST);
    float (*Ps)[AST]     = (float (*)[AST])(sm + 4 * 64 * AST);

    const int tid = threadIdx.x;
    const int lane = tid & 31;
    const int wid = tid >> 5;
    const int g = lane >> 2, t = lane & 3;
    const int qt = (gridDim.x - 1) - blockIdx.x;   // heavy tiles first
    const int b = blockIdx.y & (BATCH - 1);
    const int h = blockIdx.y / BATCH;
    const int qbase = qt * 64;
    const int qr = wid * 16;

    // Stage Q (scaled) into Ps, extract A-fragments, then free Ps.
    #pragma unroll
    for (int i = 0; i < 8; i++) {
        const int idx = tid + i * 128;           // 0..1023
        const int r = idx >> 4, cc = (idx & 15) * 4;
        float4 v = *(const float4*)(g_q + (size_t)((qbase + r) * BATCH + b) * DMODEL + h * HDIM + cc);
        Ps[r][cc + 0] = v.x * 0.125f;
        Ps[r][cc + 1] = v.y * 0.125f;
        Ps[r][cc + 2] = v.z * 0.125f;
        Ps[r][cc + 3] = v.w * 0.125f;
    }
    __syncthreads();
    unsigned qf[8][4];
    #pragma unroll
    for (int kk = 0; kk < 8; kk++) {
        qf[kk][0] = f2tf(Ps[qr + g][kk * 8 + t]);
        qf[kk][1] = f2tf(Ps[qr + 8 + g][kk * 8 + t]);
        qf[kk][2] = f2tf(Ps[qr + g][kk * 8 + 4 + t]);
        qf[kk][3] = f2tf(Ps[qr + 8 + g][kk * 8 + 4 + t]);
    }
    __syncthreads();

    float o[8][4];
    #pragma unroll
    for (int nt = 0; nt < 8; nt++)
        #pragma unroll
        for (int i = 0; i < 4; i++) o[nt][i] = 0.0f;
    float m0 = -1e30f, m1 = -1e30f, l0 = 0.0f, l1 = 0.0f;

    const int numKT = qt + 1;

    // prologue K/V tile 0
    #pragma unroll
    for (int i = 0; i < 8; i++) {
        const int idx = tid + i * 128;
        const int r = idx >> 4, cc = (idx & 15) * 4;
        const size_t go = (size_t)((0 + r) * BATCH + b) * DMODEL + h * HDIM + cc;
        cpa16(&Ks[0][r][cc], g_k + go);
        cpa16(&Vs[0][r][cc], g_v + go);
    }
    CP_COMMIT();

    for (int kt = 0; kt < numKT; kt++) {
        if (kt + 1 < numKT) {
            const int sn = (kt + 1) & 1;
            const int t0 = (kt + 1) * 64;
            #pragma unroll
            for (int i = 0; i < 8; i++) {
                const int idx = tid + i * 128;
                const int r = idx >> 4, cc = (idx & 15) * 4;
                const size_t go = (size_t)((t0 + r) * BATCH + b) * DMODEL + h * HDIM + cc;
                cpa16(&Ks[sn][r][cc], g_k + go);
                cpa16(&Vs[sn][r][cc], g_v + go);
            }
            CP_COMMIT();
            CP_WAIT1();
        } else {
            CP_WAIT0();
        }
        __syncthreads();
        const int s = kt & 1;

        // S = Q K^T  (scores for this warp's 16 rows x 64 keys)
        float sc[8][4];
        #pragma unroll
        for (int nt = 0; nt < 8; nt++) {
            sc[nt][0] = 0.f; sc[nt][1] = 0.f; sc[nt][2] = 0.f; sc[nt][3] = 0.f;
            #pragma unroll
            for (int kk = 0; kk < 8; kk++) {
                unsigned b0 = f2tf(Ks[s][nt * 8 + g][kk * 8 + t]);
                unsigned b1 = f2tf(Ks[s][nt * 8 + g][kk * 8 + 4 + t]);
                mma_tf32(sc[nt][0], sc[nt][1], sc[nt][2], sc[nt][3],
                         qf[kk][0], qf[kk][1], qf[kk][2], qf[kk][3], b0, b1);
            }
        }

        // causal mask (only the diagonal tile)
        if (kt == numKT - 1) {
            const int r0 = qbase + qr + g, r1 = r0 + 8;
            #pragma unroll
            for (int nt = 0; nt < 8; nt++) {
                const int cb = kt * 64 + nt * 8 + 2 * t;
                if (cb     > r0) sc[nt][0] = -1e30f;
                if (cb + 1 > r0) sc[nt][1] = -1e30f;
                if (cb     > r1) sc[nt][2] = -1e30f;
                if (cb + 1 > r1) sc[nt][3] = -1e30f;
            }
        }

        // online softmax
        float tm0 = -1e30f, tm1 = -1e30f;
        #pragma unroll
        for (int nt = 0; nt < 8; nt++) {
            tm0 = fmaxf(tm0, fmaxf(sc[nt][0], sc[nt][1]));
            tm1 = fmaxf(tm1, fmaxf(sc[nt][2], sc[nt][3]));
        }
        tm0 = fmaxf(tm0, __shfl_xor_sync(0xffffffffu, tm0, 1));
        tm0 = fmaxf(tm0, __shfl_xor_sync(0xffffffffu, tm0, 2));
        tm1 = fmaxf(tm1, __shfl_xor_sync(0xffffffffu, tm1, 1));
        tm1 = fmaxf(tm1, __shfl_xor_sync(0xffffffffu, tm1, 2));
        const float mn0 = fmaxf(m0, tm0), mn1 = fmaxf(m1, tm1);
        const float cr0 = __expf(m0 - mn0), cr1 = __expf(m1 - mn1);
        m0 = mn0; m1 = mn1;
        l0 *= cr0; l1 *= cr1;
        #pragma unroll
        for (int nt = 0; nt < 8; nt++) {
            o[nt][0] *= cr0; o[nt][1] *= cr0;
            o[nt][2] *= cr1; o[nt][3] *= cr1;
        }
        float ps0 = 0.f, ps1 = 0.f;
        #pragma unroll
        for (int nt = 0; nt < 8; nt++) {
            float p0 = __expf(sc[nt][0] - mn0);
            float p1 = __expf(sc[nt][1] - mn0);
            float p2 = __expf(sc[nt][2] - mn1);
            float p3 = __expf(sc[nt][3] - mn1);
            ps0 += p0 + p1; ps1 += p2 + p3;
            *(float2*)&Ps[qr + g][nt * 8 + 2 * t]     = make_float2(p0, p1);
            *(float2*)&Ps[qr + 8 + g][nt * 8 + 2 * t] = make_float2(p2, p3);
        }
        l0 += ps0; l1 += ps1;
        __syncwarp();   // Ps rows are warp-private

        // O += P V
        #pragma unroll
        for (int kk = 0; kk < 8; kk++) {
            unsigned a0 = f2tf(Ps[qr + g][kk * 8 + t]);
            unsigned a1 = f2tf(Ps[qr + 8 + g][kk * 8 + t]);
            unsigned a2 = f2tf(Ps[qr + g][kk * 8 + 4 + t]);
            unsigned a3 = f2tf(Ps[qr + 8 + g][kk * 8 + 4 + t]);
            #pragma unroll
            for (int nt = 0; nt < 8; nt++) {
                unsigned b0 = f2tf(Vs[s][kk * 8 + t][nt * 8 + g]);
                unsigned b1 = f2tf(Vs[s][kk * 8 + 4 + t][nt * 8 + g]);
                mma_tf32(o[nt][0], o[nt][1], o[nt][2], o[nt][3], a0, a1, a2, a3, b0, b1);
            }
        }
        __syncthreads();   // done reading Ks/Vs[s] before it is refilled
    }

    // normalize + store
    l0 += __shfl_xor_sync(0xffffffffu, l0, 1);
    l0 += __shfl_xor_sync(0xffffffffu, l0, 2);
    l1 += __shfl_xor_sync(0xffffffffu, l1, 1);
    l1 += __shfl_xor_sync(0xffffffffu, l1, 2);
    const float inv0 = 1.0f / l0, inv1 = 1.0f / l1;
    const int r0 = qbase + qr + g;
    #pragma unroll
    for (int nt = 0; nt < 8; nt++) {
        const int col = h * HDIM + nt * 8 + 2 * t;
        *(float2*)&g_ctx[(size_t)(r0 * BATCH + b) * DMODEL + col] =
            make_float2(o[nt][0] * inv0, o[nt][1] * inv0);
        *(float2*)&g_ctx[(size_t)((r0 + 8) * BATCH + b) * DMODEL + col] =
            make_float2(o[nt][2] * inv1, o[nt][3] * inv1);
    }
}

// ---------------- launch ----------------
#define ATTN_SMEM ((2 * 64 * AST * 2 + 64 * AST) * (int)sizeof(float))  // 87040 B

extern "C" void kernel_launch(void* const* d_in, const int* in_sizes, int n_in,
                              void* d_out, int out_size)
{
    const float* x  = (const float*)d_in[0];
    const float* qw = (const float*)d_in[1];
    const float* qb = (const float*)d_in[2];
    const float* kw = (const float*)d_in[3];
    const float* kb = (const float*)d_in[4];
    const float* vw = (const float*)d_in[5];
    const float* vb = (const float*)d_in[6];
    const float* ow = (const float*)d_in[7];
    const float* ob = (const float*)d_in[8];
    // d_in[9] = attn_mask: causal, applied analytically.
    float* out = (float*)d_out;

    void *pq, *pk, *pv, *pc;
    cudaGetSymbolAddress(&pq, g_q);
    cudaGetSymbolAddress(&pk, g_k);
    cudaGetSymbolAddress(&pv, g_v);
    cudaGetSymbolAddress(&pc, g_ctx);

    cudaFuncSetAttribute(attn_tf32, cudaFuncAttributeMaxDynamicSharedMemorySize, ATTN_SMEM);

    dim3 gg(DMODEL / 128, MROWS / 128);   // (8, 32)
    gemm_tf32<<<gg, 256>>>(x, qw, qb, (float*)pq);
    gemm_tf32<<<gg, 256>>>(x, kw, kb, (float*)pk);
    gemm_tf32<<<gg, 256>>>(x, vw, vb, (float*)pv);
    attn_tf32<<<dim3(SEQ / 64, BATCH * NHEAD), 128, ATTN_SMEM>>>();
    gemm_tf32<<<gg, 256>>>((const float*)pc, ow, ob, out);
}

// round 4
// speedup vs baseline: 3.5749x; 1.1211x over previous
#include <cuda_runtime.h>
#include <cuda_bf16.h>
#include <math.h>

#define SEQ 2048
#define BATCH 2
#define DMODEL 1024
#define NHEAD 16
#define HDIM 64
#define MROWS (SEQ * BATCH)   // 4096

// Scratch (no cudaMalloc allowed)
__device__ float g_q[MROWS * DMODEL];
__device__ float g_k[MROWS * DMODEL];
__device__ float g_v[MROWS * DMODEL];
__device__ float g_ctx[MROWS * DMODEL];
__device__ float g_xr[MROWS * DMODEL];          // tf32-rounded input
__device__ float g_w[4][DMODEL * DMODEL];       // tf32-rounded weights

// ---------------- helpers ----------------
__device__ __forceinline__ unsigned f2tf(float f) {
    unsigned u;
    asm("cvt.rna.tf32.f32 %0, %1;" : "=r"(u) : "f"(f));
    return u;
}
__device__ __forceinline__ float rnd(float f) { return __uint_as_float(f2tf(f)); }

__device__ __forceinline__ void mma_tf32(
    float& c0, float& c1, float& c2, float& c3,
    unsigned a0, unsigned a1, unsigned a2, unsigned a3,
    unsigned b0, unsigned b1)
{
    asm volatile(
        "mma.sync.aligned.m16n8k8.row.col.f32.tf32.tf32.f32 "
        "{%0,%1,%2,%3},{%4,%5,%6,%7},{%8,%9},{%0,%1,%2,%3};"
        : "+f"(c0), "+f"(c1), "+f"(c2), "+f"(c3)
        : "r"(a0), "r"(a1), "r"(a2), "r"(a3), "r"(b0), "r"(b1));
}

__device__ __forceinline__ void cpa16(void* dst, const void* src) {
    unsigned d = (unsigned)__cvta_generic_to_shared(dst);
    asm volatile("cp.async.cg.shared.global [%0], [%1], 16;" :: "r"(d), "l"(src));
}
#define CP_COMMIT() asm volatile("cp.async.commit_group;")
#define CP_WAIT1()  asm volatile("cp.async.wait_group 1;")
#define CP_WAIT0()  asm volatile("cp.async.wait_group 0;")

// ---------------- tf32 pre-round (elementwise, float4) ----------------
__global__ __launch_bounds__(256) void round_tf32_kernel(
    const float* __restrict__ in, float* __restrict__ out, int n4)
{
    int i = blockIdx.x * blockDim.x + threadIdx.x;
    if (i < n4) {
        float4 v = ((const float4*)in)[i];
        v.x = rnd(v.x); v.y = rnd(v.y); v.z = rnd(v.z); v.w = rnd(v.w);
        ((float4*)out)[i] = v;
    }
}

// ---------------- GEMM: C[M,N] = A[M,K] @ W[N,K]^T + bias ----------------
// Inputs pre-rounded to tf32 -> fragment loads are raw bit loads.
#define GBK 16
#define GST 20

__global__ __launch_bounds__(256) void gemm_tf32(
    const float* __restrict__ A, const float* __restrict__ W,
    const float* __restrict__ bias, float* __restrict__ C, int roundOut)
{
    __shared__ float As[2][128][GST];
    __shared__ float Bs[2][128][GST];
    const int tid = threadIdx.x;
    const int lane = tid & 31;
    const int wid = tid >> 5;
    const int wm = wid & 3;
    const int wn = wid >> 2;
    const int g = lane >> 2, t = lane & 3;
    const int rowBase = blockIdx.y * 128;
    const int colBase = blockIdx.x * 128;

    const int lr0 = tid >> 2;
    const int lc = (tid & 3) * 4;
    const float* Ag = A + (size_t)(rowBase + lr0) * DMODEL + lc;
    const float* Wg = W + (size_t)(colBase + lr0) * DMODEL + lc;

    float c[2][8][4];
    #pragma unroll
    for (int mt = 0; mt < 2; mt++)
        #pragma unroll
        for (int nt = 0; nt < 8; nt++)
            #pragma unroll
            for (int i = 0; i < 4; i++) c[mt][nt][i] = 0.0f;

    {
        cpa16(&As[0][lr0][lc],      Ag);
        cpa16(&As[0][lr0 + 64][lc], Ag + (size_t)64 * DMODEL);
        cpa16(&Bs[0][lr0][lc],      Wg);
        cpa16(&Bs[0][lr0 + 64][lc], Wg + (size_t)64 * DMODEL);
        CP_COMMIT();
    }

    const int NIT = DMODEL / GBK;
    for (int it = 0; it < NIT; it++) {
        if (it + 1 < NIT) {
            const int sn = (it + 1) & 1;
            const int k0 = (it + 1) * GBK;
            cpa16(&As[sn][lr0][lc],      Ag + k0);
            cpa16(&As[sn][lr0 + 64][lc], Ag + (size_t)64 * DMODEL + k0);
            cpa16(&Bs[sn][lr0][lc],      Wg + k0);
            cpa16(&Bs[sn][lr0 + 64][lc], Wg + (size_t)64 * DMODEL + k0);
            CP_COMMIT();
            CP_WAIT1();
        } else {
            CP_WAIT0();
        }
        __syncthreads();
        const int s = it & 1;
        #pragma unroll
        for (int ks = 0; ks < 2; ks++) {
            const int kk = ks * 8;
            unsigned a[2][4], bf[8][2];
            #pragma unroll
            for (int mt = 0; mt < 2; mt++) {
                const int r = wm * 32 + mt * 16;
                a[mt][0] = __float_as_uint(As[s][r + g][kk + t]);
                a[mt][1] = __float_as_uint(As[s][r + 8 + g][kk + t]);
                a[mt][2] = __float_as_uint(As[s][r + g][kk + 4 + t]);
                a[mt][3] = __float_as_uint(As[s][r + 8 + g][kk + 4 + t]);
            }
            #pragma unroll
            for (int nt = 0; nt < 8; nt++) {
                const int n = wn * 64 + nt * 8;
                bf[nt][0] = __float_as_uint(Bs[s][n + g][kk + t]);
                bf[nt][1] = __float_as_uint(Bs[s][n + g][kk + 4 + t]);
            }
            #pragma unroll
            for (int mt = 0; mt < 2; mt++)
                #pragma unroll
                for (int nt = 0; nt < 8; nt++)
                    mma_tf32(c[mt][nt][0], c[mt][nt][1], c[mt][nt][2], c[mt][nt][3],
                             a[mt][0], a[mt][1], a[mt][2], a[mt][3],
                             bf[nt][0], bf[nt][1]);
        }
        __syncthreads();
    }

    #pragma unroll
    for (int mt = 0; mt < 2; mt++) {
        const int r0 = rowBase + wm * 32 + mt * 16 + g;
        #pragma unroll
        for (int nt = 0; nt < 8; nt++) {
            const int col = colBase + wn * 64 + nt * 8 + 2 * t;
            float2 bb = *(const float2*)&bias[col];
            float v0 = c[mt][nt][0] + bb.x, v1 = c[mt][nt][1] + bb.y;
            float v2 = c[mt][nt][2] + bb.x, v3 = c[mt][nt][3] + bb.y;
            if (roundOut) { v0 = rnd(v0); v1 = rnd(v1); v2 = rnd(v2); v3 = rnd(v3); }
            *(float2*)&C[(size_t)r0 * DMODEL + col] = make_float2(v0, v1);
            *(float2*)&C[(size_t)(r0 + 8) * DMODEL + col] = make_float2(v2, v3);
        }
    }
}

// ---------------- Flash attention (causal), tf32 mma ----------------
// 128 q rows per block, 8 warps (256 thr); warp w owns rows [16w,16w+16).
// K/V tiles of 64 keys double-buffered; Q/K/V pre-rounded to tf32.
#define AST 68

__global__ __launch_bounds__(256) void attn_tf32()
{
    extern __shared__ float sm[];
    float (*Ks)[64][AST] = (float (*)[64][AST])sm;
    float (*Vs)[64][AST] = (float (*)[64][AST])(sm + 2 * 64 * AST);
    float (*Ps)[AST]     = (float (*)[AST])(sm + 4 * 64 * AST);

    const int tid = threadIdx.x;
    const int lane = tid & 31;
    const int wid = tid >> 5;
    const int g = lane >> 2, t = lane & 3;
    const int qt = (gridDim.x - 1) - blockIdx.x;   // heavy tiles first
    const int b = blockIdx.y & (BATCH - 1);
    const int h = blockIdx.y / BATCH;
    const int qbase = qt * 128;
    const int qr = wid * 16;

    // Stage Q (scaled; scaling by 2^-3 is exact on tf32 values) into Ps.
    #pragma unroll
    for (int i = 0; i < 8; i++) {
        const int idx = tid + i * 256;           // 0..2047
        const int r = idx >> 4, cc = (idx & 15) * 4;
        float4 v = *(const float4*)(g_q + (size_t)((qbase + r) * BATCH + b) * DMODEL + h * HDIM + cc);
        Ps[r][cc + 0] = v.x * 0.125f;
        Ps[r][cc + 1] = v.y * 0.125f;
        Ps[r][cc + 2] = v.z * 0.125f;
        Ps[r][cc + 3] = v.w * 0.125f;
    }
    __syncthreads();
    unsigned qf[8][4];
    #pragma unroll
    for (int kk = 0; kk < 8; kk++) {
        qf[kk][0] = __float_as_uint(Ps[qr + g][kk * 8 + t]);
        qf[kk][1] = __float_as_uint(Ps[qr + 8 + g][kk * 8 + t]);
        qf[kk][2] = __float_as_uint(Ps[qr + g][kk * 8 + 4 + t]);
        qf[kk][3] = __float_as_uint(Ps[qr + 8 + g][kk * 8 + 4 + t]);
    }
    __syncthreads();

    float o[8][4];
    #pragma unroll
    for (int nt = 0; nt < 8; nt++)
        #pragma unroll
        for (int i = 0; i < 4; i++) o[nt][i] = 0.0f;
    float m0 = -1e30f, m1 = -1e30f, l0 = 0.0f, l1 = 0.0f;

    const int numKT = 2 * qt + 2;   // 64-key tiles covering 0..qbase+127

    // prologue tile 0
    #pragma unroll
    for (int i = 0; i < 4; i++) {
        const int idx = tid + i * 256;           // 0..1023
        const int r = idx >> 4, cc = (idx & 15) * 4;
        const size_t go = (size_t)(r * BATCH + b) * DMODEL + h * HDIM + cc;
        cpa16(&Ks[0][r][cc], g_k + go);
        cpa16(&Vs[0][r][cc], g_v + go);
    }
    CP_COMMIT();

    for (int kt = 0; kt < numKT; kt++) {
        if (kt + 1 < numKT) {
            const int sn = (kt + 1) & 1;
            const int t0 = (kt + 1) * 64;
            #pragma unroll
            for (int i = 0; i < 4; i++) {
                const int idx = tid + i * 256;
                const int r = idx >> 4, cc = (idx & 15) * 4;
                const size_t go = (size_t)((t0 + r) * BATCH + b) * DMODEL + h * HDIM + cc;
                cpa16(&Ks[sn][r][cc], g_k + go);
                cpa16(&Vs[sn][r][cc], g_v + go);
            }
            CP_COMMIT();
            CP_WAIT1();
        } else {
            CP_WAIT0();
        }
        __syncthreads();
        const int s = kt & 1;

        // S = Q K^T
        float sc[8][4];
        #pragma unroll
        for (int nt = 0; nt < 8; nt++) {
            sc[nt][0] = 0.f; sc[nt][1] = 0.f; sc[nt][2] = 0.f; sc[nt][3] = 0.f;
            #pragma unroll
            for (int kk = 0; kk < 8; kk++) {
                unsigned b0 = __float_as_uint(Ks[s][nt * 8 + g][kk * 8 + t]);
                unsigned b1 = __float_as_uint(Ks[s][nt * 8 + g][kk * 8 + 4 + t]);
                mma_tf32(sc[nt][0], sc[nt][1], sc[nt][2], sc[nt][3],
                         qf[kk][0], qf[kk][1], qf[kk][2], qf[kk][3], b0, b1);
            }
        }

        // causal mask (tiles that can cross the diagonal for this warp)
        if (kt * 64 + 63 > qbase + qr) {
            const int r0 = qbase + qr + g, r1 = r0 + 8;
            #pragma unroll
            for (int nt = 0; nt < 8; nt++) {
                const int cb = kt * 64 + nt * 8 + 2 * t;
                if (cb     > r0) sc[nt][0] = -1e30f;
                if (cb + 1 > r0) sc[nt][1] = -1e30f;
                if (cb     > r1) sc[nt][2] = -1e30f;
                if (cb + 1 > r1) sc[nt][3] = -1e30f;
            }
        }

        // online softmax
        float tm0 = -1e30f, tm1 = -1e30f;
        #pragma unroll
        for (int nt = 0; nt < 8; nt++) {
            tm0 = fmaxf(tm0, fmaxf(sc[nt][0], sc[nt][1]));
            tm1 = fmaxf(tm1, fmaxf(sc[nt][2], sc[nt][3]));
        }
        tm0 = fmaxf(tm0, __shfl_xor_sync(0xffffffffu, tm0, 1));
        tm0 = fmaxf(tm0, __shfl_xor_sync(0xffffffffu, tm0, 2));
        tm1 = fmaxf(tm1, __shfl_xor_sync(0xffffffffu, tm1, 1));
        tm1 = fmaxf(tm1, __shfl_xor_sync(0xffffffffu, tm1, 2));
        const float mn0 = fmaxf(m0, tm0), mn1 = fmaxf(m1, tm1);
        const float cr0 = __expf(m0 - mn0), cr1 = __expf(m1 - mn1);
        m0 = mn0; m1 = mn1;
        l0 *= cr0; l1 *= cr1;
        #pragma unroll
        for (int nt = 0; nt < 8; nt++) {
            o[nt][0] *= cr0; o[nt][1] *= cr0;
            o[nt][2] *= cr1; o[nt][3] *= cr1;
        }
        float ps0 = 0.f, ps1 = 0.f;
        #pragma unroll
        for (int nt = 0; nt < 8; nt++) {
            float p0 = __expf(sc[nt][0] - mn0);
            float p1 = __expf(sc[nt][1] - mn0);
            float p2 = __expf(sc[nt][2] - mn1);
            float p3 = __expf(sc[nt][3] - mn1);
            ps0 += p0 + p1; ps1 += p2 + p3;
            *(float2*)&Ps[qr + g][nt * 8 + 2 * t]     = make_float2(p0, p1);
            *(float2*)&Ps[qr + 8 + g][nt * 8 + 2 * t] = make_float2(p2, p3);
        }
        l0 += ps0; l1 += ps1;
        __syncwarp();   // Ps rows are warp-private

        // O += P V
        #pragma unroll
        for (int kk = 0; kk < 8; kk++) {
            unsigned a0 = f2tf(Ps[qr + g][kk * 8 + t]);
            unsigned a1 = f2tf(Ps[qr + 8 + g][kk * 8 + t]);
            unsigned a2 = f2tf(Ps[qr + g][kk * 8 + 4 + t]);
            unsigned a3 = f2tf(Ps[qr + 8 + g][kk * 8 + 4 + t]);
            #pragma unroll
            for (int nt = 0; nt < 8; nt++) {
                unsigned b0 = __float_as_uint(Vs[s][kk * 8 + t][nt * 8 + g]);
                unsigned b1 = __float_as_uint(Vs[s][kk * 8 + 4 + t][nt * 8 + g]);
                mma_tf32(o[nt][0], o[nt][1], o[nt][2], o[nt][3], a0, a1, a2, a3, b0, b1);
            }
        }
        __syncthreads();
    }

    // normalize + store (rounded: feeds the final tf32 GEMM)
    l0 += __shfl_xor_sync(0xffffffffu, l0, 1);
    l0 += __shfl_xor_sync(0xffffffffu, l0, 2);
    l1 += __shfl_xor_sync(0xffffffffu, l1, 1);
    l1 += __shfl_xor_sync(0xffffffffu, l1, 2);
    const float inv0 = 1.0f / l0, inv1 = 1.0f / l1;
    const int r0 = qbase + qr + g;
    #pragma unroll
    for (int nt = 0; nt < 8; nt++) {
        const int col = h * HDIM + nt * 8 + 2 * t;
        *(float2*)&g_ctx[(size_t)(r0 * BATCH + b) * DMODEL + col] =
            make_float2(rnd(o[nt][0] * inv0), rnd(o[nt][1] * inv0));
        *(float2*)&g_ctx[(size_t)((r0 + 8) * BATCH + b) * DMODEL + col] =
            make_float2(rnd(o[nt][2] * inv1), rnd(o[nt][3] * inv1));
    }
}

// ---------------- launch ----------------
#define ATTN_SMEM ((2 * 64 * AST * 2 + 128 * AST) * (int)sizeof(float))  // 104448 B

extern "C" void kernel_launch(void* const* d_in, const int* in_sizes, int n_in,
                              void* d_out, int out_size)
{
    const float* x  = (const float*)d_in[0];
    const float* qw = (const float*)d_in[1];
    const float* qb = (const float*)d_in[2];
    const float* kw = (const float*)d_in[3];
    const float* kb = (const float*)d_in[4];
    const float* vw = (const float*)d_in[5];
    const float* vb = (const float*)d_in[6];
    const float* ow = (const float*)d_in[7];
    const float* ob = (const float*)d_in[8];
    // d_in[9] = attn_mask: causal, applied analytically.
    float* out = (float*)d_out;

    void *pq, *pk, *pv, *pc, *pxr, *pw;
    cudaGetSymbolAddress(&pq, g_q);
    cudaGetSymbolAddress(&pk, g_k);
    cudaGetSymbolAddress(&pv, g_v);
    cudaGetSymbolAddress(&pc, g_ctx);
    cudaGetSymbolAddress(&pxr, g_xr);
    cudaGetSymbolAddress(&pw, g_w);
    float* xr = (float*)pxr;
    float* w0 = (float*)pw;
    float* w1 = w0 + DMODEL * DMODEL;
    float* w2 = w1 + DMODEL * DMODEL;
    float* w3 = w2 + DMODEL * DMODEL;

    cudaFuncSetAttribute(attn_tf32, cudaFuncAttributeMaxDynamicSharedMemorySize, ATTN_SMEM);

    const int n4x = MROWS * DMODEL / 4;       // 1M
    const int n4w = DMODEL * DMODEL / 4;      // 256K
    round_tf32_kernel<<<n4x / 256, 256>>>(x,  xr, n4x);
    round_tf32_kernel<<<n4w / 256, 256>>>(qw, w0, n4w);
    round_tf32_kernel<<<n4w / 256, 256>>>(kw, w1, n4w);
    round_tf32_kernel<<<n4w / 256, 256>>>(vw, w2, n4w);
    round_tf32_kernel<<<n4w / 256, 256>>>(ow, w3, n4w);

    dim3 gg(DMODEL / 128, MROWS / 128);   // (8, 32)
    gemm_tf32<<<gg, 256>>>(xr, w0, qb, (float*)pq, 1);
    gemm_tf32<<<gg, 256>>>(xr, w1, kb, (float*)pk, 1);
    gemm_tf32<<<gg, 256>>>(xr, w2, vb, (float*)pv, 1);
    attn_tf32<<<dim3(SEQ / 128, BATCH * NHEAD), 256, ATTN_SMEM>>>();
    gemm_tf32<<<gg, 256>>>((const float*)pc, w3, ob, out, 0);
}

// round 6
// speedup vs baseline: 8.3845x; 2.3453x over previous
#include <cuda_runtime.h>
#include <cuda_fp16.h>
#include <math.h>
#include <stdint.h>

#define SEQ 2048
#define BATCH 2
#define DMODEL 1024
#define NHEAD 16
#define HDIM 64
#define MROWS (SEQ * BATCH)   // 4096

// Scratch (no cudaMalloc allowed) — fp16 activations/weights
__device__ __half g_q[MROWS * DMODEL];
__device__ __half g_k[MROWS * DMODEL];
__device__ __half g_v[MROWS * DMODEL];
__device__ __half g_ctx[MROWS * DMODEL];
__device__ __half g_xh[MROWS * DMODEL];
__device__ __half g_wh[4][DMODEL * DMODEL];

// ---------------- helpers ----------------
__device__ __forceinline__ void mma_f16(
    float& c0, float& c1, float& c2, float& c3,
    uint32_t a0, uint32_t a1, uint32_t a2, uint32_t a3,
    uint32_t b0, uint32_t b1)
{
    asm volatile(
        "mma.sync.aligned.m16n8k16.row.col.f32.f16.f16.f32 "
        "{%0,%1,%2,%3},{%4,%5,%6,%7},{%8,%9},{%0,%1,%2,%3};"
        : "+f"(c0), "+f"(c1), "+f"(c2), "+f"(c3)
        : "r"(a0), "r"(a1), "r"(a2), "r"(a3), "r"(b0), "r"(b1));
}

__device__ __forceinline__ void ldsm_x4(uint32_t* r, uint32_t addr) {
    asm volatile("ldmatrix.sync.aligned.m8n8.x4.shared.b16 {%0,%1,%2,%3}, [%4];"
                 : "=r"(r[0]), "=r"(r[1]), "=r"(r[2]), "=r"(r[3]) : "r"(addr));
}
__device__ __forceinline__ void ldsm_x4_trans(uint32_t* r, uint32_t addr) {
    asm volatile("ldmatrix.sync.aligned.m8n8.x4.trans.shared.b16 {%0,%1,%2,%3}, [%4];"
                 : "=r"(r[0]), "=r"(r[1]), "=r"(r[2]), "=r"(r[3]) : "r"(addr));
}

__device__ __forceinline__ void cpa16s(uint32_t dst, const void* src) {
    asm volatile("cp.async.cg.shared.global [%0], [%1], 16;" :: "r"(dst), "l"(src));
}
#define CP_COMMIT() asm volatile("cp.async.commit_group;")
#define CP_WAIT1()  asm volatile("cp.async.wait_group 1;")
#define CP_WAIT0()  asm volatile("cp.async.wait_group 0;")

__device__ __forceinline__ uint32_t smem_u32(const void* p) {
    return (uint32_t)__cvta_generic_to_shared(p);
}
__device__ __forceinline__ uint32_t sw64(uint32_t off)  { return off ^ ((off >> 3) & 0x30); }
__device__ __forceinline__ uint32_t sw128(uint32_t off) { return off ^ ((off >> 3) & 0x70); }

// ---------------- fp32 -> fp16 convert ----------------
__global__ __launch_bounds__(256) void to_half_kernel(
    const float* __restrict__ in, __half* __restrict__ out, int n4)
{
    int i = blockIdx.x * blockDim.x + threadIdx.x;
    if (i < n4) {
        float4 v = ((const float4*)in)[i];
        __half2 h0 = __floats2half2_rn(v.x, v.y);
        __half2 h1 = __floats2half2_rn(v.z, v.w);
        uint2 o = make_uint2(*(uint32_t*)&h0, *(uint32_t*)&h1);
        ((uint2*)out)[i] = o;
    }
}

// ---------------- fp16 GEMM: C[M,N] = A[M,K] @ W[N,K]^T + bias ----------------
// Block 128x128, BK=32 (64B rows, SW64), 256 thr (8 warps 4m x 2n), warp 32x64.
__global__ __launch_bounds__(256) void gemm_f16(
    const __half* __restrict__ A, const __half* __restrict__ W,
    const float* __restrict__ bias, __half* __restrict__ Ch, float* __restrict__ Cf)
{
    __shared__ __align__(1024) __half As[2][128 * 32];
    __shared__ __align__(1024) __half Bs[2][128 * 32];

    const int tid = threadIdx.x;
    const int lane = tid & 31;
    const int wid = tid >> 5;
    const int wm = wid & 3, wn = wid >> 2;
    const int g = lane >> 2, t = lane & 3;
    const int rowBase = blockIdx.y * 128;
    const int colBase = blockIdx.x * 128;

    const uint32_t aB[2] = { smem_u32(As[0]), smem_u32(As[1]) };
    const uint32_t bB[2] = { smem_u32(Bs[0]), smem_u32(Bs[1]) };

    // ldmatrix lane geometry
    const int lr = lane & 7;
    const int qlo = (lane >> 3) & 1;    // q&1
    const int qhi = lane >> 4;          // q>>1

    auto load_stage = [&](int s, int kbase) {
        #pragma unroll
        for (int i = 0; i < 2; i++) {
            const int idx = tid + i * 256;       // 0..511
            const int r = idx >> 2, c = idx & 3; // row, 16B chunk
            const uint32_t off = sw64((uint32_t)(r * 64 + c * 16));
            cpa16s(aB[s] + off, A + (size_t)(rowBase + r) * DMODEL + kbase + c * 8);
            cpa16s(bB[s] + off, W + (size_t)(colBase + r) * DMODEL + kbase + c * 8);
        }
        CP_COMMIT();
    };

    float c[2][8][4];
    #pragma unroll
    for (int mt = 0; mt < 2; mt++)
        #pragma unroll
        for (int nt = 0; nt < 8; nt++)
            #pragma unroll
            for (int i = 0; i < 4; i++) c[mt][nt][i] = 0.0f;

    load_stage(0, 0);
    load_stage(1, 32);

    const int NIT = DMODEL / 32;   // 32
    for (int it = 0; it < NIT; it++) {
        if (it + 1 < NIT) { CP_WAIT1(); } else { CP_WAIT0(); }
        __syncthreads();
        const int s = it & 1;

        #pragma unroll
        for (int ks = 0; ks < 2; ks++) {
            uint32_t a[2][4], bf[4][4];
            #pragma unroll
            for (int mt = 0; mt < 2; mt++) {
                const int row = wm * 32 + mt * 16 + qlo * 8 + lr;
                const int ch = ks * 2 + qhi;
                ldsm_x4(a[mt], aB[s] + sw64((uint32_t)(row * 64 + ch * 16)));
            }
            #pragma unroll
            for (int jp = 0; jp < 4; jp++) {
                const int row = wn * 64 + (2 * jp + qhi) * 8 + lr;
                const int ch = ks * 2 + qlo;
                ldsm_x4(bf[jp], bB[s] + sw64((uint32_t)(row * 64 + ch * 16)));
            }
            #pragma unroll
            for (int mt = 0; mt < 2; mt++)
                #pragma unroll
                for (int nt = 0; nt < 8; nt++) {
                    const int jp = nt >> 1, hi = (nt & 1) * 2;
                    mma_f16(c[mt][nt][0], c[mt][nt][1], c[mt][nt][2], c[mt][nt][3],
                            a[mt][0], a[mt][1], a[mt][2], a[mt][3],
                            bf[jp][hi], bf[jp][hi + 1]);
                }
        }
        __syncthreads();
        if (it + 2 < NIT) load_stage(s, (it + 2) * 32);
    }

    #pragma unroll
    for (int mt = 0; mt < 2; mt++) {
        const int r0 = rowBase + wm * 32 + mt * 16 + g;
        #pragma unroll
        for (int nt = 0; nt < 8; nt++) {
            const int col = colBase + wn * 64 + nt * 8 + 2 * t;
            float2 bb = *(const float2*)&bias[col];
            float v0 = c[mt][nt][0] + bb.x, v1 = c[mt][nt][1] + bb.y;
            float v2 = c[mt][nt][2] + bb.x, v3 = c[mt][nt][3] + bb.y;
            if (Ch) {
                __half2 h0 = __floats2half2_rn(v0, v1);
                __half2 h1 = __floats2half2_rn(v2, v3);
                *(uint32_t*)&Ch[(size_t)r0 * DMODEL + col] = *(uint32_t*)&h0;
                *(uint32_t*)&Ch[(size_t)(r0 + 8) * DMODEL + col] = *(uint32_t*)&h1;
            } else {
                *(float2*)&Cf[(size_t)r0 * DMODEL + col] = make_float2(v0, v1);
                *(float2*)&Cf[(size_t)(r0 + 8) * DMODEL + col] = make_float2(v2, v3);
            }
        }
    }
}

// ---------------- Flash attention (causal), fp16 mma + ldmatrix ----------------
// 128 q rows/block, 8 warps; warp w owns rows [16w,16w+16). 64-key K/V tiles
// double-buffered via cp.async. P stays in registers (C-frag == A-frag layout).
__global__ __launch_bounds__(256) void attn_f16()
{
    __shared__ __align__(1024) __half Qs[128 * 64];
    __shared__ __align__(1024) __half Ks[2][64 * 64];
    __shared__ __align__(1024) __half Vs[2][64 * 64];

    const int tid = threadIdx.x;
    const int lane = tid & 31;
    const int wid = tid >> 5;
    const int g = lane >> 2, t = lane & 3;
    const int lr = lane & 7;
    const int qlo = (lane >> 3) & 1;
    const int qhi = lane >> 4;
    const int qt = (gridDim.x - 1) - blockIdx.x;   // heavy tiles first
    const int b = blockIdx.y & (BATCH - 1);
    const int h = blockIdx.y / BATCH;
    const int qbase = qt * 128;
    const int qr = wid * 16;

    const uint32_t qB = smem_u32(Qs);
    const uint32_t kB[2] = { smem_u32(Ks[0]), smem_u32(Ks[1]) };
    const uint32_t vB[2] = { smem_u32(Vs[0]), smem_u32(Vs[1]) };

    // Stage Q scaled by 1/8 (exact in fp16)
    const __half2 scl = __floats2half2_rn(0.125f, 0.125f);
    #pragma unroll
    for (int i = 0; i < 4; i++) {
        const int idx = tid + i * 256;          // 0..1023
        const int r = idx >> 3, c8 = idx & 7;   // row, 16B chunk
        uint4 v = *(const uint4*)(g_q + (size_t)((qbase + r) * BATCH + b) * DMODEL + h * HDIM + c8 * 8);
        __half2* hp = (__half2*)&v;
        hp[0] = __hmul2(hp[0], scl); hp[1] = __hmul2(hp[1], scl);
        hp[2] = __hmul2(hp[2], scl); hp[3] = __hmul2(hp[3], scl);
        *(uint4*)(Qs + 0) ; // no-op to keep type
        *(uint4*)((char*)Qs + sw128((uint32_t)(r * 128 + c8 * 16))) = v;
    }
    __syncthreads();

    uint32_t qf[4][4];
    #pragma unroll
    for (int kc = 0; kc < 4; kc++) {
        const int row = qr + qlo * 8 + lr;
        const int ch = kc * 2 + qhi;
        ldsm_x4(qf[kc], qB + sw128((uint32_t)(row * 128 + ch * 16)));
    }
    __syncthreads();

    float o[8][4];
    #pragma unroll
    for (int nt = 0; nt < 8; nt++)
        #pragma unroll
        for (int i = 0; i < 4; i++) o[nt][i] = 0.0f;
    float m0 = -1e30f, m1 = -1e30f, l0 = 0.0f, l1 = 0.0f;

    const int numKT = 2 * qt + 2;

    auto load_kv = [&](int s, int t0) {
        #pragma unroll
        for (int i = 0; i < 2; i++) {
            const int idx = tid + i * 256;        // 0..511
            const int r = idx >> 3, c8 = idx & 7;
            const size_t go = (size_t)((t0 + r) * BATCH + b) * DMODEL + h * HDIM + c8 * 8;
            const uint32_t off = sw128((uint32_t)(r * 128 + c8 * 16));
            cpa16s(kB[s] + off, g_k + go);
            cpa16s(vB[s] + off, g_v + go);
        }
        CP_COMMIT();
    };

    load_kv(0, 0);

    for (int kt = 0; kt < numKT; kt++) {
        if (kt + 1 < numKT) { load_kv((kt + 1) & 1, (kt + 1) * 64); CP_WAIT1(); }
        else                { CP_WAIT0(); }
        __syncthreads();
        const int s = kt & 1;

        // S = Q K^T
        float sc[8][4];
        #pragma unroll
        for (int nt = 0; nt < 8; nt++) {
            sc[nt][0] = 0.f; sc[nt][1] = 0.f; sc[nt][2] = 0.f; sc[nt][3] = 0.f;
        }
        #pragma unroll
        for (int kc = 0; kc < 4; kc++) {
            uint32_t kb[4][4];
            #pragma unroll
            for (int jp = 0; jp < 4; jp++) {
                const int row = (2 * jp + qhi) * 8 + lr;
                const int ch = kc * 2 + qlo;
                ldsm_x4(kb[jp], kB[s] + sw128((uint32_t)(row * 128 + ch * 16)));
            }
            #pragma unroll
            for (int nt = 0; nt < 8; nt++) {
                const int jp = nt >> 1, hi = (nt & 1) * 2;
                mma_f16(sc[nt][0], sc[nt][1], sc[nt][2], sc[nt][3],
                        qf[kc][0], qf[kc][1], qf[kc][2], qf[kc][3],
                        kb[jp][hi], kb[jp][hi + 1]);
            }
        }

        // causal mask
        if (kt * 64 + 63 > qbase + qr) {
            const int r0 = qbase + qr + g, r1 = r0 + 8;
            #pragma unroll
            for (int nt = 0; nt < 8; nt++) {
                const int cb = kt * 64 + nt * 8 + 2 * t;
                if (cb     > r0) sc[nt][0] = -1e30f;
                if (cb + 1 > r0) sc[nt][1] = -1e30f;
                if (cb     > r1) sc[nt][2] = -1e30f;
                if (cb + 1 > r1) sc[nt][3] = -1e30f;
            }
        }

        // online softmax
        float tm0 = -1e30f, tm1 = -1e30f;
        #pragma unroll
        for (int nt = 0; nt < 8; nt++) {
            tm0 = fmaxf(tm0, fmaxf(sc[nt][0], sc[nt][1]));
            tm1 = fmaxf(tm1, fmaxf(sc[nt][2], sc[nt][3]));
        }
        tm0 = fmaxf(tm0, __shfl_xor_sync(0xffffffffu, tm0, 1));
        tm0 = fmaxf(tm0, __shfl_xor_sync(0xffffffffu, tm0, 2));
        tm1 = fmaxf(tm1, __shfl_xor_sync(0xffffffffu, tm1, 1));
        tm1 = fmaxf(tm1, __shfl_xor_sync(0xffffffffu, tm1, 2));
        const float mn0 = fmaxf(m0, tm0), mn1 = fmaxf(m1, tm1);
        const float cr0 = __expf(m0 - mn0), cr1 = __expf(m1 - mn1);
        m0 = mn0; m1 = mn1;
        l0 *= cr0; l1 *= cr1;
        #pragma unroll
        for (int nt = 0; nt < 8; nt++) {
            o[nt][0] *= cr0; o[nt][1] *= cr0;
            o[nt][2] *= cr1; o[nt][3] *= cr1;
        }
        // P = exp(S - m), pack to fp16 A-fragments in registers
        uint32_t pa[8];   // [nt] -> {rows g | g+8} pair regs
        float ps0 = 0.f, ps1 = 0.f;
        #pragma unroll
        for (int nt = 0; nt < 8; nt++) {
            float p0 = __expf(sc[nt][0] - mn0);
            float p1 = __expf(sc[nt][1] - mn0);
            float p2 = __expf(sc[nt][2] - mn1);
            float p3 = __expf(sc[nt][3] - mn1);
            ps0 += p0 + p1; ps1 += p2 + p3;
            __half2 h0 = __floats2half2_rn(p0, p1);
            __half2 h1 = __floats2half2_rn(p2, p3);
            pa[nt] = *(uint32_t*)&h0;
            pa[nt] |= 0;   // keep
            // store high rows in upper half of array via interleave below
            sc[nt][0] = __uint_as_float(*(uint32_t*)&h1);   // reuse sc as storage
        }
        l0 += ps0; l1 += ps1;

        // O += P V
        #pragma unroll
        for (int kc = 0; kc < 4; kc++) {
            const uint32_t a0 = pa[2 * kc];
            const uint32_t a1 = __float_as_uint(sc[2 * kc][0]);
            const uint32_t a2 = pa[2 * kc + 1];
            const uint32_t a3 = __float_as_uint(sc[2 * kc + 1][0]);
            #pragma unroll
            for (int jp = 0; jp < 4; jp++) {
                uint32_t vb[4];
                const int row = kc * 16 + qlo * 8 + lr;
                const int ch = 2 * jp + qhi;
                ldsm_x4_trans(vb, vB[s] + sw128((uint32_t)(row * 128 + ch * 16)));
                mma_f16(o[2*jp][0], o[2*jp][1], o[2*jp][2], o[2*jp][3],
                        a0, a1, a2, a3, vb[0], vb[1]);
                mma_f16(o[2*jp+1][0], o[2*jp+1][1], o[2*jp+1][2], o[2*jp+1][3],
                        a0, a1, a2, a3, vb[2], vb[3]);
            }
        }
        __syncthreads();
    }

    // normalize + store (fp16, feeds final GEMM)
    l0 += __shfl_xor_sync(0xffffffffu, l0, 1);
    l0 += __shfl_xor_sync(0xffffffffu, l0, 2);
    l1 += __shfl_xor_sync(0xffffffffu, l1, 1);
    l1 += __shfl_xor_sync(0xffffffffu, l1, 2);
    const float inv0 = 1.0f / l0, inv1 = 1.0f / l1;
    const int r0 = qbase + qr + g;
    #pragma unroll
    for (int nt = 0; nt < 8; nt++) {
        const int col = h * HDIM + nt * 8 + 2 * t;
        __half2 h0 = __floats2half2_rn(o[nt][0] * inv0, o[nt][1] * inv0);
        __half2 h1 = __floats2half2_rn(o[nt][2] * inv1, o[nt][3] * inv1);
        *(uint32_t*)&g_ctx[(size_t)(r0 * BATCH + b) * DMODEL + col] = *(uint32_t*)&h0;
        *(uint32_t*)&g_ctx[(size_t)((r0 + 8) * BATCH + b) * DMODEL + col] = *(uint32_t*)&h1;
    }
}

// ---------------- launch ----------------
extern "C" void kernel_launch(void* const* d_in, const int* in_sizes, int n_in,
                              void* d_out, int out_size)
{
    const float* x  = (const float*)d_in[0];
    const float* qw = (const float*)d_in[1];
    const float* qb = (const float*)d_in[2];
    const float* kw = (const float*)d_in[3];
    const float* kb = (const float*)d_in[4];
    const float* vw = (const float*)d_in[5];
    const float* vb = (const float*)d_in[6];
    const float* ow = (const float*)d_in[7];
    const float* ob = (const float*)d_in[8];
    // d_in[9] = attn_mask: causal, applied analytically.
    float* out = (float*)d_out;

    void *pq, *pk, *pv, *pc, *pxh, *pwh;
    cudaGetSymbolAddress(&pq, g_q);
    cudaGetSymbolAddress(&pk, g_k);
    cudaGetSymbolAddress(&pv, g_v);
    cudaGetSymbolAddress(&pc, g_ctx);
    cudaGetSymbolAddress(&pxh, g_xh);
    cudaGetSymbolAddress(&pwh, g_wh);
    __half* xh = (__half*)pxh;
    __half* w0 = (__half*)pwh;
    __half* w1 = w0 + DMODEL * DMODEL;
    __half* w2 = w1 + DMODEL * DMODEL;
    __half* w3 = w2 + DMODEL * DMODEL;

    const int n4x = MROWS * DMODEL / 4;
    const int n4w = DMODEL * DMODEL / 4;
    to_half_kernel<<<n4x / 256, 256>>>(x,  xh, n4x);
    to_half_kernel<<<n4w / 256, 256>>>(qw, w0, n4w);
    to_half_kernel<<<n4w / 256, 256>>>(kw, w1, n4w);
    to_half_kernel<<<n4w / 256, 256>>>(vw, w2, n4w);
    to_half_kernel<<<n4w / 256, 256>>>(ow, w3, n4w);

    dim3 gg(DMODEL / 128, MROWS / 128);   // (8, 32)
    gemm_f16<<<gg, 256>>>(xh, w0, qb, (__half*)pq, nullptr);
    gemm_f16<<<gg, 256>>>(xh, w1, kb, (__half*)pk, nullptr);
    gemm_f16<<<gg, 256>>>(xh, w2, vb, (__half*)pv, nullptr);
    attn_f16<<<dim3(SEQ / 128, BATCH * NHEAD), 256>>>();
    gemm_f16<<<gg, 256>>>((const __half*)pc, w3, ob, nullptr, out);
}

// round 10
// speedup vs baseline: 9.1240x; 1.0882x over previous
#include <cuda_runtime.h>
#include <cuda_fp16.h>
#include <math.h>
#include <stdint.h>

#define SEQ 2048
#define BATCH 2
#define DMODEL 1024
#define NHEAD 16
#define HDIM 64
#define MROWS (SEQ * BATCH)   // 4096

// Scratch (no cudaMalloc allowed) — fp16 activations/weights
__device__ __half g_q[MROWS * DMODEL];
__device__ __half g_k[MROWS * DMODEL];
__device__ __half g_v[MROWS * DMODEL];
__device__ __half g_ctx[MROWS * DMODEL];
__device__ __half g_xh[MROWS * DMODEL];
__device__ __half g_wh[4][DMODEL * DMODEL];

// ---------------- helpers ----------------
__device__ __forceinline__ void mma_f16(
    float& c0, float& c1, float& c2, float& c3,
    uint32_t a0, uint32_t a1, uint32_t a2, uint32_t a3,
    uint32_t b0, uint32_t b1)
{
    asm volatile(
        "mma.sync.aligned.m16n8k16.row.col.f32.f16.f16.f32 "
        "{%0,%1,%2,%3},{%4,%5,%6,%7},{%8,%9},{%0,%1,%2,%3};"
        : "+f"(c0), "+f"(c1), "+f"(c2), "+f"(c3)
        : "r"(a0), "r"(a1), "r"(a2), "r"(a3), "r"(b0), "r"(b1));
}

__device__ __forceinline__ void ldsm_x4(uint32_t* r, uint32_t addr) {
    asm volatile("ldmatrix.sync.aligned.m8n8.x4.shared.b16 {%0,%1,%2,%3}, [%4];"
                 : "=r"(r[0]), "=r"(r[1]), "=r"(r[2]), "=r"(r[3]) : "r"(addr));
}
__device__ __forceinline__ void ldsm_x4_trans(uint32_t* r, uint32_t addr) {
    asm volatile("ldmatrix.sync.aligned.m8n8.x4.trans.shared.b16 {%0,%1,%2,%3}, [%4];"
                 : "=r"(r[0]), "=r"(r[1]), "=r"(r[2]), "=r"(r[3]) : "r"(addr));
}

__device__ __forceinline__ float ex2(float x) {
    float r;
    asm("ex2.approx.f32 %0, %1;" : "=f"(r) : "f"(x));
    return r;
}

__device__ __forceinline__ void cpa16s(uint32_t dst, const void* src) {
    asm volatile("cp.async.cg.shared.global [%0], [%1], 16;" :: "r"(dst), "l"(src));
}
#define CP_COMMIT() asm volatile("cp.async.commit_group;")
#define CP_WAIT1()  asm volatile("cp.async.wait_group 1;")
#define CP_WAIT0()  asm volatile("cp.async.wait_group 0;")

__device__ __forceinline__ uint32_t smem_u32(const void* p) {
    return (uint32_t)__cvta_generic_to_shared(p);
}
__device__ __forceinline__ uint32_t sw64(uint32_t off)  { return off ^ ((off >> 3) & 0x30); }
__device__ __forceinline__ uint32_t sw128(uint32_t off) { return off ^ ((off >> 3) & 0x70); }

// ---------------- fused fp32 -> fp16 convert (x + 4 weights, one launch) --------
#define XBLKS (MROWS * DMODEL / 4 / 256)         // 4096
#define WBLKS (DMODEL * DMODEL / 4 / 256)        // 1024
__global__ __launch_bounds__(256) void conv_all_kernel(
    const float* __restrict__ x,
    const float* __restrict__ qw, const float* __restrict__ kw,
    const float* __restrict__ vw, const float* __restrict__ ow,
    __half* __restrict__ xh, __half* __restrict__ wh)
{
    const int bi = blockIdx.x;
    const float* src;
    __half* dst;
    int off;
    if (bi < XBLKS) {
        src = x; dst = xh; off = bi * 256;
    } else {
        const int w = (bi - XBLKS) >> 10;
        const int lb = (bi - XBLKS) & (WBLKS - 1);
        src = (w == 0) ? qw : (w == 1) ? kw : (w == 2) ? vw : ow;
        dst = wh + (size_t)w * DMODEL * DMODEL;
        off = lb * 256;
    }
    const int i = off + threadIdx.x;
    float4 v = ((const float4*)src)[i];
    __half2 h0 = __floats2half2_rn(v.x, v.y);
    __half2 h1 = __floats2half2_rn(v.z, v.w);
    ((uint2*)dst)[i] = make_uint2(*(uint32_t*)&h0, *(uint32_t*)&h1);
}

// ---------------- fp16 GEMM core (128x128 block, BK=32, 8 warps) ----------------
struct GemmOut { __half* h; float* f; };

__device__ __forceinline__ void gemm_body(
    const __half* __restrict__ A, const __half* __restrict__ W,
    const float* __restrict__ bias, __half* Ch, float* Cf,
    int rowBase, int colBase)
{
    __shared__ __align__(1024) __half As[2][128 * 32];
    __shared__ __align__(1024) __half Bs[2][128 * 32];

    const int tid = threadIdx.x;
    const int lane = tid & 31;
    const int wid = tid >> 5;
    const int wm = wid & 3, wn = wid >> 2;
    const int g = lane >> 2, t = lane & 3;

    const uint32_t aB[2] = { smem_u32(As[0]), smem_u32(As[1]) };
    const uint32_t bB[2] = { smem_u32(Bs[0]), smem_u32(Bs[1]) };

    const int lr = lane & 7;
    const int qlo = (lane >> 3) & 1;
    const int qhi = lane >> 4;

    auto load_stage = [&](int s, int kbase) {
        #pragma unroll
        for (int i = 0; i < 2; i++) {
            const int idx = tid + i * 256;
            const int r = idx >> 2, c = idx & 3;
            const uint32_t off = sw64((uint32_t)(r * 64 + c * 16));
            cpa16s(aB[s] + off, A + (size_t)(rowBase + r) * DMODEL + kbase + c * 8);
            cpa16s(bB[s] + off, W + (size_t)(colBase + r) * DMODEL + kbase + c * 8);
        }
        CP_COMMIT();
    };

    float c[2][8][4];
    #pragma unroll
    for (int mt = 0; mt < 2; mt++)
        #pragma unroll
        for (int nt = 0; nt < 8; nt++)
            #pragma unroll
            for (int i = 0; i < 4; i++) c[mt][nt][i] = 0.0f;

    load_stage(0, 0);
    load_stage(1, 32);

    const int NIT = DMODEL / 32;
    for (int it = 0; it < NIT; it++) {
        if (it + 1 < NIT) { CP_WAIT1(); } else { CP_WAIT0(); }
        __syncthreads();
        const int s = it & 1;

        #pragma unroll
        for (int ks = 0; ks < 2; ks++) {
            uint32_t a[2][4], bf[4][4];
            #pragma unroll
            for (int mt = 0; mt < 2; mt++) {
                const int row = wm * 32 + mt * 16 + qlo * 8 + lr;
                const int ch = ks * 2 + qhi;
                ldsm_x4(a[mt], aB[s] + sw64((uint32_t)(row * 64 + ch * 16)));
            }
            #pragma unroll
            for (int jp = 0; jp < 4; jp++) {
                const int row = wn * 64 + (2 * jp + qhi) * 8 + lr;
                const int ch = ks * 2 + qlo;
                ldsm_x4(bf[jp], bB[s] + sw64((uint32_t)(row * 64 + ch * 16)));
            }
            #pragma unroll
            for (int mt = 0; mt < 2; mt++)
                #pragma unroll
                for (int nt = 0; nt < 8; nt++) {
                    const int jp = nt >> 1, hi = (nt & 1) * 2;
                    mma_f16(c[mt][nt][0], c[mt][nt][1], c[mt][nt][2], c[mt][nt][3],
                            a[mt][0], a[mt][1], a[mt][2], a[mt][3],
                            bf[jp][hi], bf[jp][hi + 1]);
                }
        }
        __syncthreads();
        if (it + 2 < NIT) load_stage(s, (it + 2) * 32);
    }

    #pragma unroll
    for (int mt = 0; mt < 2; mt++) {
        const int r0 = rowBase + wm * 32 + mt * 16 + g;
        #pragma unroll
        for (int nt = 0; nt < 8; nt++) {
            const int col = colBase + wn * 64 + nt * 8 + 2 * t;
            float2 bb = *(const float2*)&bias[col];
            float v0 = c[mt][nt][0] + bb.x, v1 = c[mt][nt][1] + bb.y;
            float v2 = c[mt][nt][2] + bb.x, v3 = c[mt][nt][3] + bb.y;
            if (Ch) {
                __half2 h0 = __floats2half2_rn(v0, v1);
                __half2 h1 = __floats2half2_rn(v2, v3);
                *(uint32_t*)&Ch[(size_t)r0 * DMODEL + col] = *(uint32_t*)&h0;
                *(uint32_t*)&Ch[(size_t)(r0 + 8) * DMODEL + col] = *(uint32_t*)&h1;
            } else {
                *(float2*)&Cf[(size_t)r0 * DMODEL + col] = make_float2(v0, v1);
                *(float2*)&Cf[(size_t)(r0 + 8) * DMODEL + col] = make_float2(v2, v3);
            }
        }
    }
}

// Fused QKV projection: blockIdx.x selects weight (0..2) and N-tile (0..7)
__global__ __launch_bounds__(256) void gemm_qkv(
    const __half* __restrict__ A, const __half* __restrict__ Wbase,
    const float* __restrict__ qb, const float* __restrict__ kb,
    const float* __restrict__ vb,
    __half* __restrict__ Oq, __half* __restrict__ Ok, __half* __restrict__ Ov)
{
    const int wsel = blockIdx.x >> 3;
    const int colBase = (blockIdx.x & 7) * 128;
    const int rowBase = blockIdx.y * 128;
    const __half* W = Wbase + (size_t)wsel * DMODEL * DMODEL;
    const float* bias = (wsel == 0) ? qb : (wsel == 1) ? kb : vb;
    __half* Ch = (wsel == 0) ? Oq : (wsel == 1) ? Ok : Ov;
    gemm_body(A, W, bias, Ch, nullptr, rowBase, colBase);
}

// Output projection (fp32 out)
__global__ __launch_bounds__(256) void gemm_out(
    const __half* __restrict__ A, const __half* __restrict__ W,
    const float* __restrict__ bias, float* __restrict__ Cf)
{
    gemm_body(A, W, bias, nullptr, Cf, blockIdx.y * 128, blockIdx.x * 128);
}

// ---------------- Flash attention (causal), fp16 mma + ldmatrix ----------------
// Scores computed in log2 domain (Q pre-scaled by 0.125*log2e) -> bare ex2.
__global__ __launch_bounds__(256) void attn_f16()
{
    __shared__ __align__(1024) __half Qs[128 * 64];
    __shared__ __align__(1024) __half Ks[2][64 * 64];
    __shared__ __align__(1024) __half Vs[2][64 * 64];

    const int tid = threadIdx.x;
    const int lane = tid & 31;
    const int wid = tid >> 5;
    const int g = lane >> 2, t = lane & 3;
    const int lr = lane & 7;
    const int qlo = (lane >> 3) & 1;
    const int qhi = lane >> 4;
    const int qt = (gridDim.x - 1) - blockIdx.x;   // heavy tiles first
    const int b = blockIdx.y & (BATCH - 1);
    const int h = blockIdx.y / BATCH;
    const int qbase = qt * 128;
    const int qr = wid * 16;

    const uint32_t qB = smem_u32(Qs);
    const uint32_t kB[2] = { smem_u32(Ks[0]), smem_u32(Ks[1]) };
    const uint32_t vB[2] = { smem_u32(Vs[0]), smem_u32(Vs[1]) };

    // Stage Q scaled by log2e/8 -> scores in log2 domain
    const float qs = 0.125f * 1.4426950408889634f;
    const __half2 scl = __floats2half2_rn(qs, qs);
    #pragma unroll
    for (int i = 0; i < 4; i++) {
        const int idx = tid + i * 256;
        const int r = idx >> 3, c8 = idx & 7;
        uint4 v = *(const uint4*)(g_q + (size_t)((qbase + r) * BATCH + b) * DMODEL + h * HDIM + c8 * 8);
        __half2* hp = (__half2*)&v;
        hp[0] = __hmul2(hp[0], scl); hp[1] = __hmul2(hp[1], scl);
        hp[2] = __hmul2(hp[2], scl); hp[3] = __hmul2(hp[3], scl);
        *(uint4*)((char*)Qs + sw128((uint32_t)(r * 128 + c8 * 16))) = v;
    }
    __syncthreads();

    uint32_t qf[4][4];
    #pragma unroll
    for (int kc = 0; kc < 4; kc++) {
        const int row = qr + qlo * 8 + lr;
        const int ch = kc * 2 + qhi;
        ldsm_x4(qf[kc], qB + sw128((uint32_t)(row * 128 + ch * 16)));
    }
    __syncthreads();

    float o[8][4];
    #pragma unroll
    for (int nt = 0; nt < 8; nt++)
        #pragma unroll
        for (int i = 0; i < 4; i++) o[nt][i] = 0.0f;
    float m0 = -1e30f, m1 = -1e30f, l0 = 0.0f, l1 = 0.0f;

    const int numKT = 2 * qt + 2;

    auto load_kv = [&](int s, int t0) {
        #pragma unroll
        for (int i = 0; i < 2; i++) {
            const int idx = tid + i * 256;
            const int r = idx >> 3, c8 = idx & 7;
            const size_t go = (size_t)((t0 + r) * BATCH + b) * DMODEL + h * HDIM + c8 * 8;
            const uint32_t off = sw128((uint32_t)(r * 128 + c8 * 16));
            cpa16s(kB[s] + off, g_k + go);
            cpa16s(vB[s] + off, g_v + go);
        }
        CP_COMMIT();
    };

    load_kv(0, 0);

    for (int kt = 0; kt < numKT; kt++) {
        if (kt + 1 < numKT) { load_kv((kt + 1) & 1, (kt + 1) * 64); CP_WAIT1(); }
        else                { CP_WAIT0(); }
        __syncthreads();
        const int s = kt & 1;

        // S = Q K^T (log2 domain)
        float sc[8][4];
        #pragma unroll
        for (int nt = 0; nt < 8; nt++) {
            sc[nt][0] = 0.f; sc[nt][1] = 0.f; sc[nt][2] = 0.f; sc[nt][3] = 0.f;
        }
        #pragma unroll
        for (int kc = 0; kc < 4; kc++) {
            uint32_t kb[4][4];
            #pragma unroll
            for (int jp = 0; jp < 4; jp++) {
                const int row = (2 * jp + qhi) * 8 + lr;
                const int ch = kc * 2 + qlo;
                ldsm_x4(kb[jp], kB[s] + sw128((uint32_t)(row * 128 + ch * 16)));
            }
            #pragma unroll
            for (int nt = 0; nt < 8; nt++) {
                const int jp = nt >> 1, hi = (nt & 1) * 2;
                mma_f16(sc[nt][0], sc[nt][1], sc[nt][2], sc[nt][3],
                        qf[kc][0], qf[kc][1], qf[kc][2], qf[kc][3],
                        kb[jp][hi], kb[jp][hi + 1]);
            }
        }

        // causal mask
        if (kt * 64 + 63 > qbase + qr) {
            const int r0 = qbase + qr + g, r1 = r0 + 8;
            #pragma unroll
            for (int nt = 0; nt < 8; nt++) {
                const int cb = kt * 64 + nt * 8 + 2 * t;
                if (cb     > r0) sc[nt][0] = -1e30f;
                if (cb + 1 > r0) sc[nt][1] = -1e30f;
                if (cb     > r1) sc[nt][2] = -1e30f;
                if (cb + 1 > r1) sc[nt][3] = -1e30f;
            }
        }

        // online softmax (log2 domain)
        float tm0 = -1e30f, tm1 = -1e30f;
        #pragma unroll
        for (int nt = 0; nt < 8; nt++) {
            tm0 = fmaxf(tm0, fmaxf(sc[nt][0], sc[nt][1]));
            tm1 = fmaxf(tm1, fmaxf(sc[nt][2], sc[nt][3]));
        }
        tm0 = fmaxf(tm0, __shfl_xor_sync(0xffffffffu, tm0, 1));
        tm0 = fmaxf(tm0, __shfl_xor_sync(0xffffffffu, tm0, 2));
        tm1 = fmaxf(tm1, __shfl_xor_sync(0xffffffffu, tm1, 1));
        tm1 = fmaxf(tm1, __shfl_xor_sync(0xffffffffu, tm1, 2));
        const float mn0 = fmaxf(m0, tm0), mn1 = fmaxf(m1, tm1);
        const float cr0 = ex2(m0 - mn0), cr1 = ex2(m1 - mn1);
        m0 = mn0; m1 = mn1;
        l0 *= cr0; l1 *= cr1;
        #pragma unroll
        for (int nt = 0; nt < 8; nt++) {
            o[nt][0] *= cr0; o[nt][1] *= cr0;
            o[nt][2] *= cr1; o[nt][3] *= cr1;
        }
        uint32_t paLo[8], paHi[8];
        float ps0 = 0.f, ps1 = 0.f;
        #pragma unroll
        for (int nt = 0; nt < 8; nt++) {
            float p0 = ex2(sc[nt][0] - mn0);
            float p1 = ex2(sc[nt][1] - mn0);
            float p2 = ex2(sc[nt][2] - mn1);
            float p3 = ex2(sc[nt][3] - mn1);
            ps0 += p0 + p1; ps1 += p2 + p3;
            __half2 h0 = __floats2half2_rn(p0, p1);
            __half2 h1 = __floats2half2_rn(p2, p3);
            paLo[nt] = *(uint32_t*)&h0;
            paHi[nt] = *(uint32_t*)&h1;
        }
        l0 += ps0; l1 += ps1;

        // O += P V
        #pragma unroll
        for (int kc = 0; kc < 4; kc++) {
            const uint32_t a0 = paLo[2 * kc];
            const uint32_t a1 = paHi[2 * kc];
            const uint32_t a2 = paLo[2 * kc + 1];
            const uint32_t a3 = paHi[2 * kc + 1];
            #pragma unroll
            for (int jp = 0; jp < 4; jp++) {
                uint32_t vb[4];
                const int row = kc * 16 + qlo * 8 + lr;
                const int ch = 2 * jp + qhi;
                ldsm_x4_trans(vb, vB[s] + sw128((uint32_t)(row * 128 + ch * 16)));
                mma_f16(o[2*jp][0], o[2*jp][1], o[2*jp][2], o[2*jp][3],
                        a0, a1, a2, a3, vb[0], vb[1]);
                mma_f16(o[2*jp+1][0], o[2*jp+1][1], o[2*jp+1][2], o[2*jp+1][3],
                        a0, a1, a2, a3, vb[2], vb[3]);
            }
        }
        __syncthreads();
    }

    // normalize + store fp16
    l0 += __shfl_xor_sync(0xffffffffu, l0, 1);
    l0 += __shfl_xor_sync(0xffffffffu, l0, 2);
    l1 += __shfl_xor_sync(0xffffffffu, l1, 1);
    l1 += __shfl_xor_sync(0xffffffffu, l1, 2);
    const float inv0 = 1.0f / l0, inv1 = 1.0f / l1;
    const int r0 = qbase + qr + g;
    #pragma unroll
    for (int nt = 0; nt < 8; nt++) {
        const int col = h * HDIM + nt * 8 + 2 * t;
        __half2 h0 = __floats2half2_rn(o[nt][0] * inv0, o[nt][1] * inv0);
        __half2 h1 = __floats2half2_rn(o[nt][2] * inv1, o[nt][3] * inv1);
        *(uint32_t*)&g_ctx[(size_t)(r0 * BATCH + b) * DMODEL + col] = *(uint32_t*)&h0;
        *(uint32_t*)&g_ctx[(size_t)((r0 + 8) * BATCH + b) * DMODEL + col] = *(uint32_t*)&h1;
    }
}

// ---------------- launch ----------------
extern "C" void kernel_launch(void* const* d_in, const int* in_sizes, int n_in,
                              void* d_out, int out_size)
{
    const float* x  = (const float*)d_in[0];
    const float* qw = (const float*)d_in[1];
    const float* qb = (const float*)d_in[2];
    const float* kw = (const float*)d_in[3];
    const float* kb = (const float*)d_in[4];
    const float* vw = (const float*)d_in[5];
    const float* vb = (const float*)d_in[6];
    const float* ow = (const float*)d_in[7];
    const float* ob = (const float*)d_in[8];
    // d_in[9] = attn_mask: causal, applied analytically.
    float* out = (float*)d_out;

    void *pq, *pk, *pv, *pc, *pxh, *pwh;
    cudaGetSymbolAddress(&pq, g_q);
    cudaGetSymbolAddress(&pk, g_k);
    cudaGetSymbolAddress(&pv, g_v);
    cudaGetSymbolAddress(&pc, g_ctx);
    cudaGetSymbolAddress(&pxh, g_xh);
    cudaGetSymbolAddress(&pwh, g_wh);
    __half* xh = (__half*)pxh;
    __half* wh = (__half*)pwh;
    __half* w3 = wh + (size_t)3 * DMODEL * DMODEL;

    conv_all_kernel<<<XBLKS + 4 * WBLKS, 256>>>(x, qw, kw, vw, ow, xh, wh);

    gemm_qkv<<<dim3(24, MROWS / 128), 256>>>(xh, wh, qb, kb, vb,
                                             (__half*)pq, (__half*)pk, (__half*)pv);
    attn_f16<<<dim3(SEQ / 128, BATCH * NHEAD), 256>>>();
    gemm_out<<<dim3(DMODEL / 128, MROWS / 128), 256>>>((const __half*)pc, w3, ob, out);
}